// round 1
// baseline (speedup 1.0000x reference)
#include <cuda_runtime.h>
#include <math.h>

#define L 8
#define E 8
#define R 64
#define H 2048
#define TOK 8192            // BSZ*SEQ = 4*2048
#define SCALING 0.5f        // R / ALPHA_R

#define TILE_M 64
#define MAXTILES (TOK / TILE_M + E)   // 136: worst-case tiles across all experts

// ---------------- scratch (static device globals; no runtime alloc) --------
__device__ float g_xmix[(size_t)TOK * H];   // 64 MB mixed activations
__device__ float g_h[(size_t)TOK * R];     // 2 MB low-rank activations
__device__ int   g_gid[TOK];
__device__ float g_coef[TOK];
__device__ int   g_counts[E];
__device__ int   g_off[E];
__device__ int   g_cursor[E];
__device__ int   g_tilestart[E + 1];
__device__ int   g_list[TOK];

// ---------------- tiny bookkeeping kernels ---------------------------------
__global__ void reset_kernel() {
    if (threadIdx.x < E) g_counts[threadIdx.x] = 0;
}

__global__ void plan_kernel() {
    if (threadIdx.x == 0) {
        int off = 0, ts = 0;
        for (int e = 0; e < E; e++) {
            g_off[e] = off;
            g_tilestart[e] = ts;
            g_cursor[e] = 0;
            off += g_counts[e];
            ts += (g_counts[e] + TILE_M - 1) / TILE_M;
        }
        g_tilestart[E] = ts;
    }
}

__global__ void scatter_kernel() {
    int t = blockIdx.x * blockDim.x + threadIdx.x;
    if (t < TOK) {
        int e = g_gid[t];
        int pos = g_off[e] + atomicAdd(&g_cursor[e], 1);
        g_list[pos] = t;
    }
}

// ---------------- fused residual-mix + gating (warp per token) -------------
__global__ void __launch_bounds__(256) mix_gate_kernel(
    const float* __restrict__ xprev,
    const float* __restrict__ hx,
    const float* __restrict__ gw,      // [E,H] for this layer
    const float* __restrict__ gates, int layer)
{
    int warp = threadIdx.x >> 5, lane = threadIdx.x & 31;
    int t = blockIdx.x * 8 + warp;

    float z = 1.0f / (1.0f + expf(-gates[layer]));
    float omz = 1.0f - z;

    const float* xp = xprev + (size_t)t * H;
    const float* hp = hx    + (size_t)t * H;
    float*       xm = g_xmix + (size_t)t * H;

    float acc[E];
#pragma unroll
    for (int e = 0; e < E; e++) acc[e] = 0.f;

#pragma unroll 4
    for (int j = 0; j < H / 128; j++) {
        int k = j * 128 + lane * 4;
        float4 a = *(const float4*)(xp + k);
        float4 b = *(const float4*)(hp + k);
        float4 v;
        v.x = z * a.x + omz * b.x;
        v.y = z * a.y + omz * b.y;
        v.z = z * a.z + omz * b.z;
        v.w = z * a.w + omz * b.w;
        *(float4*)(xm + k) = v;
#pragma unroll
        for (int e = 0; e < E; e++) {
            float4 w = *(const float4*)(gw + (size_t)e * H + k);
            acc[e] += v.x * w.x + v.y * w.y + v.z * w.z + v.w * w.w;
        }
    }
    // warp-wide reduction of the 8 logits
#pragma unroll
    for (int e = 0; e < E; e++)
#pragma unroll
        for (int o = 16; o > 0; o >>= 1)
            acc[e] += __shfl_xor_sync(0xffffffffu, acc[e], o);

    if (lane == 0) {
        float m = acc[0]; int g = 0;
#pragma unroll
        for (int e = 1; e < E; e++) if (acc[e] > m) { m = acc[e]; g = e; }  // first-max tie-break
        float s = 0.f;
#pragma unroll
        for (int e = 0; e < E; e++) s += expf(acc[e] - m);
        g_gid[t]  = g;
        g_coef[t] = SCALING / s;        // SCALING * softmax prob of argmax
        atomicAdd(&g_counts[g], 1);
    }
}

// ---------------- A projection: h[tok, r] = A[e] @ xmix[tok] ---------------
// Per expert GEMM: M=cnt tokens, N=R=64, K=H=2048. Tile 64x64, BK=16.
__global__ void __launch_bounds__(256) aproj_kernel(const float* __restrict__ A)
{
    __shared__ float Xs[16][68];   // [k][m]
    __shared__ float As[16][68];   // [k][n]
    __shared__ int   s_tok[64];

    int gt = blockIdx.x;
    if (gt >= g_tilestart[E]) return;
    int e = 0;
    while (gt >= g_tilestart[e + 1]) e++;
    int tile = gt - g_tilestart[e];
    int cnt  = g_counts[e];
    int base = g_off[e] + tile * 64;

    int tid = threadIdx.x;
    if (tid < 64)
        s_tok[tid] = (tile * 64 + tid < cnt) ? g_list[base + tid] : -1;
    __syncthreads();

    const float* Ae = A + (size_t)e * R * H;

    int row = tid >> 2;        // 0..63
    int q   = tid & 3;         // 0..3 -> k sub-offset q*4
    int tx  = tid & 15, ty = tid >> 4;

    int tokr = s_tok[row];
    const float* xrow = (tokr >= 0) ? (g_xmix + (size_t)tokr * H) : g_xmix;
    bool xvalid = (tokr >= 0);
    const float* arow = Ae + (size_t)row * H;

    float acc[4][4];
#pragma unroll
    for (int i = 0; i < 4; i++)
#pragma unroll
        for (int j = 0; j < 4; j++) acc[i][j] = 0.f;

    for (int k0 = 0; k0 < H; k0 += 16) {
        float4 xv = xvalid ? *(const float4*)(xrow + k0 + q * 4) : make_float4(0, 0, 0, 0);
        float4 av = *(const float4*)(arow + k0 + q * 4);
        Xs[q * 4 + 0][row] = xv.x; Xs[q * 4 + 1][row] = xv.y;
        Xs[q * 4 + 2][row] = xv.z; Xs[q * 4 + 3][row] = xv.w;
        As[q * 4 + 0][row] = av.x; As[q * 4 + 1][row] = av.y;
        As[q * 4 + 2][row] = av.z; As[q * 4 + 3][row] = av.w;
        __syncthreads();
#pragma unroll
        for (int kk = 0; kk < 16; kk++) {
            float4 xm4 = *(const float4*)&Xs[kk][ty * 4];
            float4 an4 = *(const float4*)&As[kk][tx * 4];
            acc[0][0] += xm4.x * an4.x; acc[0][1] += xm4.x * an4.y;
            acc[0][2] += xm4.x * an4.z; acc[0][3] += xm4.x * an4.w;
            acc[1][0] += xm4.y * an4.x; acc[1][1] += xm4.y * an4.y;
            acc[1][2] += xm4.y * an4.z; acc[1][3] += xm4.y * an4.w;
            acc[2][0] += xm4.z * an4.x; acc[2][1] += xm4.z * an4.y;
            acc[2][2] += xm4.z * an4.z; acc[2][3] += xm4.z * an4.w;
            acc[3][0] += xm4.w * an4.x; acc[3][1] += xm4.w * an4.y;
            acc[3][2] += xm4.w * an4.z; acc[3][3] += xm4.w * an4.w;
        }
        __syncthreads();
    }
#pragma unroll
    for (int i = 0; i < 4; i++) {
        int tok = s_tok[ty * 4 + i];
        if (tok >= 0) {
            float4 o = make_float4(acc[i][0], acc[i][1], acc[i][2], acc[i][3]);
            *(float4*)(g_h + (size_t)tok * R + tx * 4) = o;
        }
    }
}

// ---------------- B projection: y[tok, h] = coef * (B[e] @ h[tok]) ---------
// Per expert GEMM: M=cnt tokens, N=64 h-slice, K=R=64 (single pass).
__global__ void __launch_bounds__(256) bproj_kernel(const float* __restrict__ Bm,
                                                    float* __restrict__ y)
{
    __shared__ float Hs[64][68];   // [r][m]
    __shared__ float Bs[64][68];   // [r][n]
    __shared__ int   s_tok[64];

    int gt = blockIdx.x;
    if (gt >= g_tilestart[E]) return;
    int e = 0;
    while (gt >= g_tilestart[e + 1]) e++;
    int tile = gt - g_tilestart[e];
    int cnt  = g_counts[e];
    int base = g_off[e] + tile * 64;
    int h0   = blockIdx.y * 64;

    int tid = threadIdx.x;
    if (tid < 64)
        s_tok[tid] = (tile * 64 + tid < cnt) ? g_list[base + tid] : -1;
    __syncthreads();

    int row = tid >> 2;    // 0..63
    int q   = tid & 3;     // 0..3

    {
        int tok = s_tok[row];
        const float* hr = (tok >= 0) ? (g_h + (size_t)tok * R) : g_h;
        bool hv = (tok >= 0);
#pragma unroll
        for (int c = 0; c < 4; c++) {
            int r = c * 16 + q * 4;
            float4 v = hv ? *(const float4*)(hr + r) : make_float4(0, 0, 0, 0);
            Hs[r + 0][row] = v.x; Hs[r + 1][row] = v.y;
            Hs[r + 2][row] = v.z; Hs[r + 3][row] = v.w;
        }
        const float* br = Bm + ((size_t)e * H + (size_t)(h0 + row)) * R;
#pragma unroll
        for (int c = 0; c < 4; c++) {
            int r = c * 16 + q * 4;
            float4 v = *(const float4*)(br + r);
            Bs[r + 0][row] = v.x; Bs[r + 1][row] = v.y;
            Bs[r + 2][row] = v.z; Bs[r + 3][row] = v.w;
        }
    }
    __syncthreads();

    int tx = tid & 15, ty = tid >> 4;
    float acc[4][4];
#pragma unroll
    for (int i = 0; i < 4; i++)
#pragma unroll
        for (int j = 0; j < 4; j++) acc[i][j] = 0.f;

#pragma unroll 16
    for (int rr = 0; rr < 64; rr++) {
        float4 hm = *(const float4*)&Hs[rr][ty * 4];
        float4 bn = *(const float4*)&Bs[rr][tx * 4];
        acc[0][0] += hm.x * bn.x; acc[0][1] += hm.x * bn.y;
        acc[0][2] += hm.x * bn.z; acc[0][3] += hm.x * bn.w;
        acc[1][0] += hm.y * bn.x; acc[1][1] += hm.y * bn.y;
        acc[1][2] += hm.y * bn.z; acc[1][3] += hm.y * bn.w;
        acc[2][0] += hm.z * bn.x; acc[2][1] += hm.z * bn.y;
        acc[2][2] += hm.z * bn.z; acc[2][3] += hm.z * bn.w;
        acc[3][0] += hm.w * bn.x; acc[3][1] += hm.w * bn.y;
        acc[3][2] += hm.w * bn.z; acc[3][3] += hm.w * bn.w;
    }

#pragma unroll
    for (int i = 0; i < 4; i++) {
        int tok = s_tok[ty * 4 + i];
        if (tok >= 0) {
            float c = g_coef[tok];
            float4 o = make_float4(acc[i][0] * c, acc[i][1] * c,
                                   acc[i][2] * c, acc[i][3] * c);
            *(float4*)(y + (size_t)tok * H + h0 + tx * 4) = o;
        }
    }
}

// ---------------- launcher --------------------------------------------------
extern "C" void kernel_launch(void* const* d_in, const int* in_sizes, int n_in,
                              void* d_out, int out_size)
{
    const float* hs    = (const float*)d_in[0];  // [L+1, B, S, H]
    const float* gates = (const float*)d_in[1];  // [L]
    const float* A     = (const float*)d_in[2];  // [L, E, R, H]
    const float* Bm    = (const float*)d_in[3];  // [L, E, H, R]
    const float* gw    = (const float*)d_in[4];  // [L, E, H]
    float* y = (float*)d_out;                    // [B, S, H]

    const size_t HS = (size_t)TOK * H;

    for (int i = 0; i < L; i++) {
        // reference: h_x = hs[1] for layers 0 and 1, then hs[i] for i>=2
        const float* xprev = (i == 0) ? hs : y;
        const float* hx    = hs + (size_t)((i == 0) ? 1 : i) * HS;

        reset_kernel<<<1, 32>>>();
        mix_gate_kernel<<<TOK / 8, 256>>>(xprev, hx, gw + (size_t)i * E * H, gates, i);
        plan_kernel<<<1, 32>>>();
        scatter_kernel<<<TOK / 256, 256>>>();
        aproj_kernel<<<MAXTILES, 256>>>(A + (size_t)i * E * R * H);
        bproj_kernel<<<dim3(MAXTILES, H / 64), 256>>>(Bm + (size_t)i * E * H * R, y);
    }
}

// round 2
// speedup vs baseline: 1.2089x; 1.2089x over previous
#include <cuda_runtime.h>
#include <math.h>

#define L 8
#define E 8
#define R 64
#define H 2048
#define TOK 8192            // BSZ*SEQ
#define SCALING 0.5f        // R / ALPHA_R

#define TM 128              // token tile
#define KSPLIT 4
#define KCH (H / KSPLIT)    // 512
#define BK 32
#define XS 36               // Xs row stride (floats): 32 + 4 pad, 16B-aligned rows
#define HSS 68              // bproj smem row stride: 64 + 4 pad
#define NTILES (TOK / TM + E)   // 72 worst-case tiles

#define FMA2(acc, a, b) asm("fma.rn.f32x2 %0, %1, %2, %0;" : "+l"(acc) : "l"(a), "l"(b))

typedef unsigned long long ull;

// ---------------- scratch --------------------------------------------------
__device__ float g_xmix[(size_t)TOK * H];        // 64 MB
__device__ float g_hpart[KSPLIT][(size_t)TOK * R];
__device__ float g_h[(size_t)TOK * R];
__device__ int   g_gid[TOK];
__device__ float g_coef[TOK];
__device__ int   g_counts[E];
__device__ int   g_cnt[E];
__device__ int   g_off[E];
__device__ int   g_cursor[E];
__device__ int   g_tilestart[E + 1];
__device__ int   g_list[TOK];

// ---------------- bookkeeping ----------------------------------------------
__global__ void reset_kernel() {
    if (threadIdx.x < E) g_counts[threadIdx.x] = 0;
}

// plan also saves counts and re-zeroes them for the next layer's mix atomics
__global__ void plan_kernel() {
    if (threadIdx.x == 0) {
        int off = 0, ts = 0;
        for (int e = 0; e < E; e++) {
            int c = g_counts[e];
            g_cnt[e] = c;
            g_off[e] = off;
            g_tilestart[e] = ts;
            g_cursor[e] = 0;
            g_counts[e] = 0;
            off += c;
            ts += (c + TM - 1) / TM;
        }
        g_tilestart[E] = ts;
    }
}

__global__ void scatter_kernel() {
    int t = blockIdx.x * blockDim.x + threadIdx.x;
    if (t < TOK) {
        int e = g_gid[t];
        int pos = g_off[e] + atomicAdd(&g_cursor[e], 1);
        g_list[pos] = t;
    }
}

// ---------------- fused residual-mix + gating (warp per token) -------------
__global__ void __launch_bounds__(256) mix_gate_kernel(
    const float* __restrict__ xprev,
    const float* __restrict__ hx,
    const float* __restrict__ gw,
    const float* __restrict__ gates, int layer)
{
    int warp = threadIdx.x >> 5, lane = threadIdx.x & 31;
    int t = blockIdx.x * 8 + warp;

    float z = 1.0f / (1.0f + expf(-gates[layer]));
    float omz = 1.0f - z;

    const float* xp = xprev + (size_t)t * H;
    const float* hp = hx    + (size_t)t * H;
    float*       xm = g_xmix + (size_t)t * H;

    float acc[E];
#pragma unroll
    for (int e = 0; e < E; e++) acc[e] = 0.f;

#pragma unroll 4
    for (int j = 0; j < H / 128; j++) {
        int k = j * 128 + lane * 4;
        float4 a = *(const float4*)(xp + k);
        float4 b = *(const float4*)(hp + k);
        float4 v;
        v.x = z * a.x + omz * b.x;
        v.y = z * a.y + omz * b.y;
        v.z = z * a.z + omz * b.z;
        v.w = z * a.w + omz * b.w;
        *(float4*)(xm + k) = v;
#pragma unroll
        for (int e = 0; e < E; e++) {
            float4 w = *(const float4*)(gw + (size_t)e * H + k);
            acc[e] += v.x * w.x + v.y * w.y + v.z * w.z + v.w * w.w;
        }
    }
#pragma unroll
    for (int e = 0; e < E; e++)
#pragma unroll
        for (int o = 16; o > 0; o >>= 1)
            acc[e] += __shfl_xor_sync(0xffffffffu, acc[e], o);

    if (lane == 0) {
        float m = acc[0]; int g = 0;
#pragma unroll
        for (int e = 1; e < E; e++) if (acc[e] > m) { m = acc[e]; g = e; }
        float s = 0.f;
#pragma unroll
        for (int e = 0; e < E; e++) s += expf(acc[e] - m);
        g_gid[t]  = g;
        g_coef[t] = SCALING / s;
        atomicAdd(&g_counts[g], 1);
    }
}

// ---------------- A projection (k-split): hpart[p][tok,r] -------------------
// Tile: 128 tokens x 64 r, K-chunk = 512. 128 threads, 8x8 per thread,
// f32x2 K-pair packed accumulation.
__global__ void __launch_bounds__(128) aproj_kernel(const float* __restrict__ A)
{
    __shared__ __align__(16) float Xs[TM * XS];
    __shared__ __align__(16) float As[R * XS];
    __shared__ int s_tok[TM];

    int gt = blockIdx.x;
    if (gt >= g_tilestart[E]) return;
    int part = blockIdx.y;
    int e = 0;
    while (gt >= g_tilestart[e + 1]) e++;
    int tile = gt - g_tilestart[e];
    int cnt  = g_cnt[e];
    int base = g_off[e] + tile * TM;

    int tid = threadIdx.x;
    s_tok[tid] = (tile * TM + tid < cnt) ? g_list[base + tid] : -1;
    __syncthreads();

    int tm = tid >> 3, tn = tid & 7;

    ull acc[8][8];
#pragma unroll
    for (int i = 0; i < 8; i++)
#pragma unroll
        for (int j = 0; j < 8; j++) acc[i][j] = 0ULL;

    int tok = s_tok[tid];
    const float* xrow = (tok >= 0) ? (g_xmix + (size_t)tok * H + part * KCH) : nullptr;
    int ar = tid & 63, ahf = tid >> 6;
    const float* arow = A + (size_t)e * R * H + (size_t)ar * H + part * KCH + ahf * 16;

    const ull* Xs64 = (const ull*)Xs;
    const ull* As64 = (const ull*)As;

    for (int k0 = 0; k0 < KCH; k0 += BK) {
        __syncthreads();
        if (tok >= 0) {
#pragma unroll
            for (int q = 0; q < 8; q++)
                *(float4*)&Xs[tid * XS + q * 4] = *(const float4*)(xrow + k0 + q * 4);
        } else {
            float4 zz = make_float4(0, 0, 0, 0);
#pragma unroll
            for (int q = 0; q < 8; q++) *(float4*)&Xs[tid * XS + q * 4] = zz;
        }
#pragma unroll
        for (int q = 0; q < 4; q++)
            *(float4*)&As[ar * XS + ahf * 16 + q * 4] = *(const float4*)(arow + k0 + q * 4);
        __syncthreads();

#pragma unroll 2
        for (int kp = 0; kp < BK / 2; kp++) {
            ull xv[8], bv[8];
#pragma unroll
            for (int i = 0; i < 8; i++) xv[i] = Xs64[(tm + 16 * i) * (XS / 2) + kp];
#pragma unroll
            for (int j = 0; j < 8; j++) bv[j] = As64[(tn + 8 * j) * (XS / 2) + kp];
#pragma unroll
            for (int i = 0; i < 8; i++)
#pragma unroll
                for (int j = 0; j < 8; j++) FMA2(acc[i][j], xv[i], bv[j]);
        }
    }

    float* hp = g_hpart[part];
#pragma unroll
    for (int i = 0; i < 8; i++) {
        int m = tm + 16 * i;
        int t2 = s_tok[m];
        if (t2 >= 0) {
#pragma unroll
            for (int j = 0; j < 8; j++) {
                ull a = acc[i][j];
                float lo = __uint_as_float((unsigned)a);
                float hi = __uint_as_float((unsigned)(a >> 32));
                hp[(size_t)t2 * R + tn + 8 * j] = lo + hi;
            }
        }
    }
}

// ---------------- reduce 4 K-partials (deterministic) -----------------------
__global__ void hreduce_kernel() {
    int i = blockIdx.x * 256 + threadIdx.x;   // over TOK*R/4 float4s
    const float4* p0 = (const float4*)g_hpart[0];
    const float4* p1 = (const float4*)g_hpart[1];
    const float4* p2 = (const float4*)g_hpart[2];
    const float4* p3 = (const float4*)g_hpart[3];
    float4 a = p0[i], b = p1[i], c = p2[i], d = p3[i];
    float4 o;
    o.x = (a.x + b.x) + (c.x + d.x);
    o.y = (a.y + b.y) + (c.y + d.y);
    o.z = (a.z + b.z) + (c.z + d.z);
    o.w = (a.w + b.w) + (c.w + d.w);
    ((float4*)g_h)[i] = o;
}

// ---------------- B projection: y[tok, h0+n] = coef * (h . B) ---------------
// Tile: 128 tokens x 64 h-cols, K = R = 64 loaded once. f32x2 K-pair packed.
__global__ void __launch_bounds__(128) bproj_kernel(const float* __restrict__ Bm,
                                                    float* __restrict__ y)
{
    extern __shared__ __align__(16) float dsm[];
    float* Hs = dsm;                  // [TM][HSS]
    float* Bs = dsm + TM * HSS;       // [64][HSS]
    __shared__ int s_tok[TM];

    int gt = blockIdx.x;
    if (gt >= g_tilestart[E]) return;
    int e = 0;
    while (gt >= g_tilestart[e + 1]) e++;
    int tile = gt - g_tilestart[e];
    int cnt  = g_cnt[e];
    int base = g_off[e] + tile * TM;
    int h0   = blockIdx.y * 64;

    int tid = threadIdx.x;
    s_tok[tid] = (tile * TM + tid < cnt) ? g_list[base + tid] : -1;
    __syncthreads();

    {
        int tok = s_tok[tid];
        if (tok >= 0) {
            const float4* hr = (const float4*)(g_h + (size_t)tok * R);
#pragma unroll
            for (int q = 0; q < 16; q++) *(float4*)&Hs[tid * HSS + q * 4] = hr[q];
        } else {
            float4 zz = make_float4(0, 0, 0, 0);
#pragma unroll
            for (int q = 0; q < 16; q++) *(float4*)&Hs[tid * HSS + q * 4] = zz;
        }
        int r = tid & 63, hf = tid >> 6;
        const float* br = Bm + ((size_t)e * H + (size_t)(h0 + r)) * R + hf * 32;
#pragma unroll
        for (int q = 0; q < 8; q++)
            *(float4*)&Bs[r * HSS + hf * 32 + q * 4] = *(const float4*)(br + q * 4);
    }
    __syncthreads();

    int tm = tid >> 3, tn = tid & 7;
    const ull* Hs64 = (const ull*)Hs;
    const ull* Bs64 = (const ull*)Bs;

    ull acc[8][8];
#pragma unroll
    for (int i = 0; i < 8; i++)
#pragma unroll
        for (int j = 0; j < 8; j++) acc[i][j] = 0ULL;

#pragma unroll 2
    for (int kp = 0; kp < R / 2; kp++) {
        ull xv[8], bv[8];
#pragma unroll
        for (int i = 0; i < 8; i++) xv[i] = Hs64[(tm + 16 * i) * (HSS / 2) + kp];
#pragma unroll
        for (int j = 0; j < 8; j++) bv[j] = Bs64[(tn + 8 * j) * (HSS / 2) + kp];
#pragma unroll
        for (int i = 0; i < 8; i++)
#pragma unroll
            for (int j = 0; j < 8; j++) FMA2(acc[i][j], xv[i], bv[j]);
    }

#pragma unroll
    for (int i = 0; i < 8; i++) {
        int m = tm + 16 * i;
        int tok = s_tok[m];
        if (tok >= 0) {
            float c = __ldg(&g_coef[tok]);
            float* yr = y + (size_t)tok * H + h0;
#pragma unroll
            for (int j = 0; j < 8; j++) {
                ull a = acc[i][j];
                float lo = __uint_as_float((unsigned)a);
                float hi = __uint_as_float((unsigned)(a >> 32));
                yr[tn + 8 * j] = (lo + hi) * c;
            }
        }
    }
}

// ---------------- launcher --------------------------------------------------
extern "C" void kernel_launch(void* const* d_in, const int* in_sizes, int n_in,
                              void* d_out, int out_size)
{
    const float* hs    = (const float*)d_in[0];  // [L+1, B, S, H]
    const float* gates = (const float*)d_in[1];  // [L]
    const float* A     = (const float*)d_in[2];  // [L, E, R, H]
    const float* Bm    = (const float*)d_in[3];  // [L, E, H, R]
    const float* gw    = (const float*)d_in[4];  // [L, E, H]
    float* y = (float*)d_out;                    // [B, S, H]

    const size_t HS = (size_t)TOK * H;
    const int SMEMB = (TM + 64) * HSS * sizeof(float);   // 52224 B

    cudaFuncSetAttribute(bproj_kernel,
                         cudaFuncAttributeMaxDynamicSharedMemorySize, SMEMB);

    reset_kernel<<<1, 32>>>();
    for (int i = 0; i < L; i++) {
        const float* xprev = (i == 0) ? hs : y;
        const float* hx    = hs + (size_t)((i == 0) ? 1 : i) * HS;

        mix_gate_kernel<<<TOK / 8, 256>>>(xprev, hx, gw + (size_t)i * E * H, gates, i);
        plan_kernel<<<1, 32>>>();
        scatter_kernel<<<TOK / 256, 256>>>();
        aproj_kernel<<<dim3(NTILES, KSPLIT), 128>>>(A + (size_t)i * E * R * H);
        hreduce_kernel<<<TOK * R / 4 / 256, 256>>>();
        bproj_kernel<<<dim3(NTILES, 32), 128, SMEMB>>>(Bm + (size_t)i * E * H * R, y);
    }
}